// round 4
// baseline (speedup 1.0000x reference)
#include <cuda_runtime.h>
#include <cstdint>

#define NN   50000
#define EE   800000
#define INF  512
#define HF   128
#define OF   64

// ---------------- scratch (static device globals; no allocation allowed) ----
__device__ float g_WAT[(size_t)NN * HF];       // WA transposed: [N, H]
__device__ float g_cat[(size_t)NN * 2 * HF];   // [N, 256]  (xA | xX)
__device__ float g_h1 [(size_t)NN * HF];       // [N, 128]
__device__ float g_t  [(size_t)NN * HF];       // [N, 128] relu(f1) pre-BN
__device__ int   g_hist[NN];
__device__ int   g_off [NN + 1];
__device__ int   g_cur [NN];
__device__ int   g_dst [EE];
__device__ int   g_rmin;
__device__ float g_sum  [HF];
__device__ float g_sumsq[HF];
__device__ float g_Wf2p [OF * HF];
__device__ float g_bf2p [OF];

// ---------------- init: zero hist + BN accumulators, reset rmin -------------
__global__ void k_init() {
    int i = blockIdx.x * blockDim.x + threadIdx.x;
    if (i < NN) g_hist[i] = 0;
    if (blockIdx.x == 0) {
        if (threadIdx.x < HF) { g_sum[threadIdx.x] = 0.f; g_sumsq[threadIdx.x] = 0.f; }
        if (threadIdx.x == 0) g_rmin = 0x7fffffff;
    }
}

// ---------------- histogram of row values + global row min ------------------
__global__ void k_hist(const int* __restrict__ row, int E) {
    int e = blockIdx.x * blockDim.x + threadIdx.x;
    int r = 0x7fffffff;
    if (e < E) {
        r = row[e];
        atomicAdd(&g_hist[r], 1);
    }
    unsigned wm = __reduce_min_sync(0xffffffffu, (unsigned)r);
    if ((threadIdx.x & 31) == 0) atomicMin(&g_rmin, (int)wm);
}

// ---------------- single-block exclusive scan over hist ---------------------
__global__ void k_scan(int E) {
    __shared__ int ssum[1024];
    int tid = threadIdx.x;
    const int chunk = (NN + 1023) / 1024;
    int beg = tid * chunk;
    int end = min(beg + chunk, NN);
    int s = 0;
    for (int i = beg; i < end; ++i) s += g_hist[i];
    ssum[tid] = s;
    __syncthreads();
    for (int ofs = 1; ofs < 1024; ofs <<= 1) {
        int v = (tid >= ofs) ? ssum[tid - ofs] : 0;
        __syncthreads();
        ssum[tid] += v;
        __syncthreads();
    }
    int run = (tid == 0) ? 0 : ssum[tid - 1];
    for (int i = beg; i < end; ++i) {
        g_off[i] = run;
        g_cur[i] = run;
        run += g_hist[i];
    }
    if (tid == 1023) g_off[NN] = run;  // == E
}

// ---------------- bin edges by row ------------------------------------------
__global__ void k_bin(const int* __restrict__ row, const int* __restrict__ col, int E) {
    int e = blockIdx.x * blockDim.x + threadIdx.x;
    if (e >= E) return;
    int r = row[e];
    int p = atomicAdd(&g_cur[r], 1);
    g_dst[p] = col[e];
}

// ---------------- transpose WA [H,N] -> WAT [N,H] ---------------------------
__global__ void k_transpose(const float* __restrict__ WA) {
    __shared__ float tile[32][33];
    int n0 = blockIdx.x * 32;
    int h0 = blockIdx.y * 32;
    int tx = threadIdx.x, ty = threadIdx.y;   // 32 x 8
    #pragma unroll
    for (int j = 0; j < 32; j += 8) {
        int h = h0 + ty + j, n = n0 + tx;
        tile[ty + j][tx] = (n < NN) ? WA[(size_t)h * NN + n] : 0.f;
    }
    __syncthreads();
    #pragma unroll
    for (int j = 0; j < 32; j += 8) {
        int n = n0 + ty + j, h = h0 + tx;
        if (n < NN) g_WAT[(size_t)n * HF + h] = tile[tx][ty + j];
    }
}

// ---------------- per-node gather: xA = segsum(WAT[col]) + bA ---------------
// one warp per node; lane handles 4 contiguous floats (float4)
__global__ void k_gather(const float* __restrict__ bA) {
    int w    = (blockIdx.x * blockDim.x + threadIdx.x) >> 5;
    int lane = threadIdx.x & 31;
    if (w >= NN) return;
    int rmin = g_rmin;
    int bkt = w + rmin;
    int s = 0, e = 0;
    if (bkt < NN) { s = g_off[bkt]; e = g_off[bkt + 1]; }
    float4 acc = *(const float4*)(bA + lane * 4);
    for (int j = s; j < e; ++j) {
        int c = g_dst[j];
        float4 v = *(const float4*)(g_WAT + (size_t)c * HF + lane * 4);
        acc.x += v.x; acc.y += v.y; acc.z += v.z; acc.w += v.w;
    }
    *((float4*)(g_cat + (size_t)w * (2 * HF) + lane * 4)) = acc;
}

// ---------------- generic tiled SGEMM: C = A[M,K] @ B[N,K]^T + bias ---------
// EPI 0: plain   EPI 1: + skip(cat[:, :128] + cat[:, 128:]) then relu   EPI 2: relu
template<int BM, int BN, int BK, int TM, int TN, int EPI>
__global__ __launch_bounds__((BM / TM) * (BN / TN))
void k_gemm(const float* __restrict__ A, int lda,
            const float* __restrict__ B,
            const float* __restrict__ bias,
            float* __restrict__ C, int ldc,
            int M, int K,
            const float* __restrict__ skipA) {
    constexpr int THREADS = (BM / TM) * (BN / TN);
    __shared__ float As[BK][BM];
    __shared__ float Bs[BK][BN];
    const int tid = threadIdx.x;
    const int bm  = blockIdx.x * BM;
    const int tx  = tid % (BN / TN);
    const int ty  = tid / (BN / TN);

    float acc[TM][TN];
    #pragma unroll
    for (int i = 0; i < TM; ++i)
        #pragma unroll
        for (int j = 0; j < TN; ++j) acc[i][j] = 0.f;

    for (int k0 = 0; k0 < K; k0 += BK) {
        constexpr int AF4 = BM * BK / 4;
        for (int idx = tid; idx < AF4; idx += THREADS) {
            int r  = idx / (BK / 4);
            int kc = (idx % (BK / 4)) * 4;
            float4 v = make_float4(0.f, 0.f, 0.f, 0.f);
            int m = bm + r;
            if (m < M) v = *(const float4*)(A + (size_t)m * lda + k0 + kc);
            As[kc + 0][r] = v.x; As[kc + 1][r] = v.y;
            As[kc + 2][r] = v.z; As[kc + 3][r] = v.w;
        }
        constexpr int BF4 = BN * BK / 4;
        for (int idx = tid; idx < BF4; idx += THREADS) {
            int n  = idx / (BK / 4);
            int kc = (idx % (BK / 4)) * 4;
            float4 v = *(const float4*)(B + (size_t)n * K + k0 + kc);
            Bs[kc + 0][n] = v.x; Bs[kc + 1][n] = v.y;
            Bs[kc + 2][n] = v.z; Bs[kc + 3][n] = v.w;
        }
        __syncthreads();
        #pragma unroll
        for (int kk = 0; kk < BK; ++kk) {
            float ra[TM], rb[TN];
            #pragma unroll
            for (int i = 0; i < TM; ++i) ra[i] = As[kk][ty * TM + i];
            #pragma unroll
            for (int j = 0; j < TN; ++j) rb[j] = Bs[kk][tx * TN + j];
            #pragma unroll
            for (int i = 0; i < TM; ++i)
                #pragma unroll
                for (int j = 0; j < TN; ++j)
                    acc[i][j] = fmaf(ra[i], rb[j], acc[i][j]);
        }
        __syncthreads();
    }

    #pragma unroll
    for (int i = 0; i < TM; ++i) {
        int m = bm + ty * TM + i;
        if (m >= M) continue;
        #pragma unroll
        for (int j = 0; j < TN; ++j) {
            int n = tx * TN + j;
            float v = acc[i][j] + bias[n];
            if (EPI == 1) {
                v += skipA[(size_t)m * 256 + n] + skipA[(size_t)m * 256 + 128 + n];
                v = fmaxf(v, 0.f);
            } else if (EPI == 2) {
                v = fmaxf(v, 0.f);
            }
            C[(size_t)m * ldc + n] = v;
        }
    }
}

// ---------------- BN statistics over g_t ------------------------------------
__global__ void k_bnstats(int M) {
    __shared__ float s_s[2][HF], s_q[2][HF];
    int c = threadIdx.x & (HF - 1);
    int g = threadIdx.x >> 7;           // 0..1 with 256 threads
    float s = 0.f, q = 0.f;
    for (int r = blockIdx.x * 2 + g; r < M; r += gridDim.x * 2) {
        float v = g_t[(size_t)r * HF + c];
        s += v; q += v * v;
    }
    s_s[g][c] = s; s_q[g][c] = q;
    __syncthreads();
    if (g == 0) {
        atomicAdd(&g_sum[c],   s_s[0][c] + s_s[1][c]);
        atomicAdd(&g_sumsq[c], s_q[0][c] + s_q[1][c]);
    }
}

// ---------------- fold BN affine into Wf2 / bf2 -----------------------------
__global__ void k_fold(const float* __restrict__ gamma, const float* __restrict__ beta,
                       const float* __restrict__ Wf2,   const float* __restrict__ bf2,
                       int M) {
    __shared__ float a[HF], b[HF];
    int t = threadIdx.x;
    if (t < HF) {
        float inv  = 1.f / (float)M;
        float mean = g_sum[t] * inv;
        float var  = g_sumsq[t] * inv - mean * mean;
        float av   = gamma[t] * rsqrtf(var + 1e-5f);
        a[t] = av;
        b[t] = beta[t] - mean * av;
    }
    __syncthreads();
    for (int i = t; i < OF * HF; i += blockDim.x)
        g_Wf2p[i] = Wf2[i] * a[i & (HF - 1)];
    if (t < OF) {
        float s = bf2[t];
        for (int h = 0; h < HF; ++h) s += b[h] * Wf2[t * HF + h];
        g_bf2p[t] = s;
    }
}

// ----------------------------------------------------------------------------
extern "C" void kernel_launch(void* const* d_in, const int* in_sizes, int n_in,
                              void* d_out, int out_size) {
    const float* x     = (const float*)d_in[0];
    const int*   ei    = (const int*)  d_in[1];
    const float* WA    = (const float*)d_in[2];
    const float* bA    = (const float*)d_in[3];
    const float* WX    = (const float*)d_in[4];
    const float* bX    = (const float*)d_in[5];
    const float* W     = (const float*)d_in[6];
    const float* bW    = (const float*)d_in[7];
    const float* Wf1   = (const float*)d_in[8];
    const float* bf1   = (const float*)d_in[9];
    const float* gamma = (const float*)d_in[10];
    const float* beta  = (const float*)d_in[11];
    const float* Wf2   = (const float*)d_in[12];
    const float* bf2   = (const float*)d_in[13];
    float* out = (float*)d_out;

    const int E = in_sizes[1] / 2;
    const int M = NN;
    const int* row = ei;
    const int* col = ei + E;

    float *pWAT, *pCat, *pH1, *pT, *pW2, *pB2;
    cudaGetSymbolAddress((void**)&pWAT, g_WAT);
    cudaGetSymbolAddress((void**)&pCat, g_cat);
    cudaGetSymbolAddress((void**)&pH1,  g_h1);
    cudaGetSymbolAddress((void**)&pT,   g_t);
    cudaGetSymbolAddress((void**)&pW2,  g_Wf2p);
    cudaGetSymbolAddress((void**)&pB2,  g_bf2p);

    // ---- edge pipeline -----------------------------------------------------
    k_init<<<(NN + 255) / 256, 256>>>();
    k_hist<<<(E + 255) / 256, 256>>>(row, E);
    k_scan<<<1, 1024>>>(E);
    k_bin<<<(E + 255) / 256, 256>>>(row, col, E);
    k_transpose<<<dim3((NN + 31) / 32, HF / 32), dim3(32, 8)>>>(WA);
    k_gather<<<(NN * 32 + 255) / 256, 256>>>(bA);       // xA -> cat[:, :128]

    // ---- xX = x @ WX^T + bX  -> cat[:, 128:] -------------------------------
    int gb = (M + 63) / 64;
    k_gemm<64, 128, 16, 4, 8, 0><<<gb, 256>>>(x, INF, WX, bX, pCat + HF, 2 * HF, M, INF, nullptr);

    // ---- h1 = relu(cat @ W^T + bW + xA + xX) -------------------------------
    k_gemm<64, 128, 16, 4, 8, 1><<<gb, 256>>>(pCat, 2 * HF, W, bW, pH1, HF, M, 2 * HF, pCat);

    // ---- t = relu(h1 @ Wf1^T + bf1) ----------------------------------------
    k_gemm<64, 128, 16, 4, 8, 2><<<gb, 256>>>(pH1, HF, Wf1, bf1, pT, HF, M, HF, nullptr);

    // ---- BN stats + fold into Wf2' -----------------------------------------
    k_bnstats<<<200, 256>>>(M);
    k_fold<<<1, 256>>>(gamma, beta, Wf2, bf2, M);

    // ---- out = bn(t) @ Wf2^T + bf2  (folded) -------------------------------
    k_gemm<64, 64, 16, 4, 8, 0><<<gb, 128>>>(pT, HF, pW2, pB2, out, OF, M, HF, nullptr);
}

// round 6
// speedup vs baseline: 2.3914x; 2.3914x over previous
#include <cuda_runtime.h>
#include <cstdint>

#define NN   50000
#define NP   50048            // padded rows = 391 * 128
#define EE   800000
#define INF  512
#define HF   128
#define OF   64
#define GBLK 391              // ceil(50000/128)

// ---------------- scratch (static device globals; zero-initialized) ---------
__device__ float g_x   [(size_t)NP * INF];     // rounded+padded x
__device__ float g_WAT [(size_t)NN * HF];      // WA transposed: [N, H]
__device__ float g_cat [(size_t)NP * 2 * HF];  // [NP, 256]  (xA | xX), tail rows stay 0
__device__ float g_h1  [(size_t)NP * HF];
__device__ float g_t   [(size_t)NP * HF];
__device__ float g_WXr [HF * INF];             // rna-rounded weights
__device__ float g_Wr  [HF * 2 * HF];
__device__ float g_Wf1r[HF * HF];
__device__ float g_Wf2p[OF * HF];              // BN-folded + rounded
__device__ float g_bf2p[OF];
__device__ int   g_hist[NN];
__device__ int   g_off [NN + 1];
__device__ int   g_cur [NN];
__device__ int   g_dst [EE];
__device__ int   g_rmin;
__device__ float g_sum  [HF];
__device__ float g_sumsq[HF];

// ---------------- helpers ----------------------------------------------------
__device__ __forceinline__ float rna(float f) {
    float r; asm("cvt.rna.tf32.f32 %0, %1;" : "=f"(r) : "f"(f)); return r;
}
__device__ __forceinline__ uint32_t s2u(const void* p) {
    uint32_t a;
    asm("{ .reg .u64 t; cvta.to.shared.u64 t, %1; cvt.u32.u64 %0, t; }" : "=r"(a) : "l"(p));
    return a;
}
__device__ __forceinline__ void cp8(uint32_t d, const void* s) {
    asm volatile("cp.async.ca.shared.global [%0], [%1], 8;" :: "r"(d), "l"(s));
}

// ---------------- init -------------------------------------------------------
__global__ void k_init() {
    int i = blockIdx.x * blockDim.x + threadIdx.x;
    if (i < NN) g_hist[i] = 0;
    if (blockIdx.x == 0) {
        if (threadIdx.x < HF) { g_sum[threadIdx.x] = 0.f; g_sumsq[threadIdx.x] = 0.f; }
        if (threadIdx.x == 0) g_rmin = 0x7fffffff;
    }
}

// ---------------- histogram + row min ----------------------------------------
__global__ void k_hist(const int* __restrict__ row, int E) {
    int e = blockIdx.x * blockDim.x + threadIdx.x;
    int r = 0x7fffffff;
    if (e < E) { r = row[e]; atomicAdd(&g_hist[r], 1); }
    unsigned wm = __reduce_min_sync(0xffffffffu, (unsigned)r);
    if ((threadIdx.x & 31) == 0) atomicMin(&g_rmin, (int)wm);
}

// ---------------- single-block exclusive scan --------------------------------
__global__ void k_scan(int E) {
    __shared__ int ssum[1024];
    int tid = threadIdx.x;
    const int chunk = (NN + 1023) / 1024;
    int beg = tid * chunk;
    int end = min(beg + chunk, NN);
    int s = 0;
    for (int i = beg; i < end; ++i) s += g_hist[i];
    ssum[tid] = s;
    __syncthreads();
    for (int ofs = 1; ofs < 1024; ofs <<= 1) {
        int v = (tid >= ofs) ? ssum[tid - ofs] : 0;
        __syncthreads();
        ssum[tid] += v;
        __syncthreads();
    }
    int run = (tid == 0) ? 0 : ssum[tid - 1];
    for (int i = beg; i < end; ++i) {
        g_off[i] = run; g_cur[i] = run; run += g_hist[i];
    }
    if (tid == 1023) g_off[NN] = run;
}

// ---------------- bin edges by row -------------------------------------------
__global__ void k_bin(const int* __restrict__ row, const int* __restrict__ col, int E) {
    int e = blockIdx.x * blockDim.x + threadIdx.x;
    if (e >= E) return;
    int r = row[e];
    int p = atomicAdd(&g_cur[r], 1);
    g_dst[p] = col[e];
}

// ---------------- transpose WA [H,N] -> WAT [N,H] ----------------------------
__global__ void k_transpose(const float* __restrict__ WA) {
    __shared__ float tile[32][33];
    int n0 = blockIdx.x * 32, h0 = blockIdx.y * 32;
    int tx = threadIdx.x, ty = threadIdx.y;
    #pragma unroll
    for (int j = 0; j < 32; j += 8) {
        int h = h0 + ty + j, n = n0 + tx;
        tile[ty + j][tx] = (n < NN) ? WA[(size_t)h * NN + n] : 0.f;
    }
    __syncthreads();
    #pragma unroll
    for (int j = 0; j < 32; j += 8) {
        int n = n0 + ty + j, h = h0 + tx;
        if (n < NN) g_WAT[(size_t)n * HF + h] = tile[tx][ty + j];
    }
}

// ---------------- gather xA = segsum(WAT[col]) + bA -> cat[:, :128] ----------
__global__ void k_gather(const float* __restrict__ bA) {
    int w    = (blockIdx.x * blockDim.x + threadIdx.x) >> 5;
    int lane = threadIdx.x & 31;
    if (w >= NN) return;
    int bkt = w + g_rmin;
    int s = 0, e = 0;
    if (bkt < NN) { s = g_off[bkt]; e = g_off[bkt + 1]; }
    float4 acc = *(const float4*)(bA + lane * 4);
    for (int j = s; j < e; ++j) {
        int c = g_dst[j];
        float4 v = *(const float4*)(g_WAT + (size_t)c * HF + lane * 4);
        acc.x += v.x; acc.y += v.y; acc.z += v.z; acc.w += v.w;
    }
    acc.x = rna(acc.x); acc.y = rna(acc.y); acc.z = rna(acc.z); acc.w = rna(acc.w);
    *((float4*)(g_cat + (size_t)w * (2 * HF) + lane * 4)) = acc;
}

// ---------------- prep: round x into padded g_x ------------------------------
__global__ void k_prep_x(const float* __restrict__ x) {
    size_t i = (size_t)blockIdx.x * blockDim.x + threadIdx.x;       // float4 index
    if (i >= (size_t)NP * INF / 4) return;
    size_t m = i / (INF / 4);
    float4 v = make_float4(0.f, 0.f, 0.f, 0.f);
    if (m < NN) v = ((const float4*)x)[i];
    v.x = rna(v.x); v.y = rna(v.y); v.z = rna(v.z); v.w = rna(v.w);
    ((float4*)g_x)[i] = v;
}

// ---------------- round weights ----------------------------------------------
__global__ void k_round_w(const float* __restrict__ WX, const float* __restrict__ W,
                          const float* __restrict__ Wf1) {
    int i = blockIdx.x * blockDim.x + threadIdx.x;
    if (i < HF * INF)    g_WXr[i]  = rna(WX[i]);
    if (i < HF * 2 * HF) g_Wr[i]   = rna(W[i]);
    if (i < HF * HF)     g_Wf1r[i] = rna(Wf1[i]);
}

// ---------------- tf32 mma.sync GEMM: C = A[M,K] @ B[N,K]^T + bias -----------
// EPI 0: plain  1: +skip(cat lo+hi)+relu  2: relu.   RND: rna-round stores.
// BM=128, BK=16, 256 thr (8 warps, 2x4), warp tile 64 x (BN/4).
template<int BN, int EPI, int RND>
__global__ __launch_bounds__(256)
void k_mm(const float* __restrict__ A, int lda,
          const float* __restrict__ B,
          const float* __restrict__ bias,
          float* __restrict__ C, int ldc, int K,
          const float* __restrict__ skip)
{
    constexpr int BM = 128, BK = 16, STR = 20;    // STR floats per row (conflict-free)
    constexpr int WX = 4, WTN = BN / WX;          // warp tile N: 32 or 16
    constexpr int NF = WTN / 8;                   // 4 or 2
    constexpr int MF = 4;                         // 64/16
    __shared__ float As[2][BM * STR];
    __shared__ float Bs[2][BN * STR];

    const int tid  = threadIdx.x;
    const int lane = tid & 31, warp = tid >> 5;
    const int wy = warp / WX, wx = warp % WX;
    const int g = lane >> 2, tg = lane & 3;
    const int bm = blockIdx.x * BM;

    float acc[MF][NF][4];
    #pragma unroll
    for (int i = 0; i < MF; ++i)
        #pragma unroll
        for (int j = 0; j < NF; ++j)
            #pragma unroll
            for (int c = 0; c < 4; ++c) acc[i][j][c] = 0.f;

    const uint32_t aS = s2u(As), bS = s2u(Bs);
    const int T = K / BK;

    // ---- async tile loader (8B chunks; 8 chunks per row of 16 floats) -------
    auto load_tiles = [&](int t, int st) {
        const int k0 = t * BK;
        #pragma unroll
        for (int i = 0; i < BM * 8 / 256; ++i) {       // A: 4 chunks/thread
            int idx = tid + i * 256;
            int r = idx >> 3, ch = idx & 7;
            cp8(aS + (uint32_t)(st * BM * STR + r * STR + ch * 2) * 4,
                A + (size_t)(bm + r) * lda + k0 + ch * 2);
        }
        #pragma unroll
        for (int i = 0; i < BN * 8 / 256; ++i) {       // B
            int idx = tid + i * 256;
            int r = idx >> 3, ch = idx & 7;
            cp8(bS + (uint32_t)(st * BN * STR + r * STR + ch * 2) * 4,
                B + (size_t)r * K + k0 + ch * 2);
        }
        asm volatile("cp.async.commit_group;");
    };

    load_tiles(0, 0);

    for (int t = 0; t < T; ++t) {
        const int cur = t & 1;
        if (t + 1 < T) {
            load_tiles(t + 1, cur ^ 1);
            asm volatile("cp.async.wait_group 1;");
        } else {
            asm volatile("cp.async.wait_group 0;");
        }
        __syncthreads();

        const float* as = As[cur];
        const float* bs = Bs[cur];
        #pragma unroll
        for (int ks = 0; ks < 2; ++ks) {
            uint32_t af[MF][4], bf[NF][2];
            #pragma unroll
            for (int mf = 0; mf < MF; ++mf) {
                int r0 = (wy * 64 + mf * 16 + g) * STR + ks * 8 + tg;
                af[mf][0] = __float_as_uint(as[r0]);
                af[mf][1] = __float_as_uint(as[r0 + 8 * STR]);
                af[mf][2] = __float_as_uint(as[r0 + 4]);
                af[mf][3] = __float_as_uint(as[r0 + 8 * STR + 4]);
            }
            #pragma unroll
            for (int nf = 0; nf < NF; ++nf) {
                int rb = (wx * WTN + nf * 8 + g) * STR + ks * 8 + tg;
                bf[nf][0] = __float_as_uint(bs[rb]);
                bf[nf][1] = __float_as_uint(bs[rb + 4]);
            }
            #pragma unroll
            for (int mf = 0; mf < MF; ++mf)
                #pragma unroll
                for (int nf = 0; nf < NF; ++nf)
                    asm volatile(
                        "mma.sync.aligned.m16n8k8.row.col.f32.tf32.tf32.f32 "
                        "{%0,%1,%2,%3},{%4,%5,%6,%7},{%8,%9},{%0,%1,%2,%3};"
                        : "+f"(acc[mf][nf][0]), "+f"(acc[mf][nf][1]),
                          "+f"(acc[mf][nf][2]), "+f"(acc[mf][nf][3])
                        : "r"(af[mf][0]), "r"(af[mf][1]), "r"(af[mf][2]), "r"(af[mf][3]),
                          "r"(bf[nf][0]), "r"(bf[nf][1]));
        }
        __syncthreads();
    }

    // ---- epilogue -----------------------------------------------------------
    #pragma unroll
    for (int mf = 0; mf < MF; ++mf) {
        #pragma unroll
        for (int nf = 0; nf < NF; ++nf) {
            int n0 = wx * WTN + nf * 8 + tg * 2;
            float b0 = bias[n0], b1 = bias[n0 + 1];
            #pragma unroll
            for (int half = 0; half < 2; ++half) {
                int m = bm + wy * 64 + mf * 16 + g + half * 8;
                if (m >= NN) continue;
                float v0 = acc[mf][nf][half * 2 + 0] + b0;
                float v1 = acc[mf][nf][half * 2 + 1] + b1;
                if (EPI == 1) {
                    const float* sp = skip + (size_t)m * 256;
                    v0 += sp[n0]     + sp[128 + n0];
                    v1 += sp[n0 + 1] + sp[128 + n0 + 1];
                    v0 = fmaxf(v0, 0.f); v1 = fmaxf(v1, 0.f);
                } else if (EPI == 2) {
                    v0 = fmaxf(v0, 0.f); v1 = fmaxf(v1, 0.f);
                }
                if (RND) { v0 = rna(v0); v1 = rna(v1); }
                *(float2*)(C + (size_t)m * ldc + n0) = make_float2(v0, v1);
            }
        }
    }
}

// ---------------- BN statistics over g_t -------------------------------------
__global__ void k_bnstats(int M) {
    __shared__ float s_s[2][HF], s_q[2][HF];
    int c = threadIdx.x & (HF - 1);
    int g = threadIdx.x >> 7;
    float s = 0.f, q = 0.f;
    for (int r = blockIdx.x * 2 + g; r < M; r += gridDim.x * 2) {
        float v = g_t[(size_t)r * HF + c];
        s += v; q += v * v;
    }
    s_s[g][c] = s; s_q[g][c] = q;
    __syncthreads();
    if (g == 0) {
        atomicAdd(&g_sum[c],   s_s[0][c] + s_s[1][c]);
        atomicAdd(&g_sumsq[c], s_q[0][c] + s_q[1][c]);
    }
}

// ---------------- fold BN affine into Wf2/bf2 --------------------------------
__global__ void k_fold(const float* __restrict__ gamma, const float* __restrict__ beta,
                       const float* __restrict__ Wf2,   const float* __restrict__ bf2,
                       int M) {
    __shared__ float a[HF], b[HF];
    int t = threadIdx.x;
    if (t < HF) {
        float inv  = 1.f / (float)M;
        float mean = g_sum[t] * inv;
        float var  = g_sumsq[t] * inv - mean * mean;
        float av   = gamma[t] * rsqrtf(var + 1e-5f);
        a[t] = av;
        b[t] = beta[t] - mean * av;
    }
    __syncthreads();
    for (int i = t; i < OF * HF; i += blockDim.x)
        g_Wf2p[i] = rna(Wf2[i] * a[i & (HF - 1)]);
    if (t < OF) {
        float s = bf2[t];
        for (int h = 0; h < HF; ++h) s += b[h] * Wf2[t * HF + h];
        g_bf2p[t] = s;
    }
}

// -----------------------------------------------------------------------------
extern "C" void kernel_launch(void* const* d_in, const int* in_sizes, int n_in,
                              void* d_out, int out_size) {
    const float* x     = (const float*)d_in[0];
    const int*   ei    = (const int*)  d_in[1];
    const float* WA    = (const float*)d_in[2];
    const float* bA    = (const float*)d_in[3];
    const float* WX    = (const float*)d_in[4];
    const float* bX    = (const float*)d_in[5];
    const float* W     = (const float*)d_in[6];
    const float* bW    = (const float*)d_in[7];
    const float* Wf1   = (const float*)d_in[8];
    const float* bf1   = (const float*)d_in[9];
    const float* gamma = (const float*)d_in[10];
    const float* beta  = (const float*)d_in[11];
    const float* Wf2   = (const float*)d_in[12];
    const float* bf2   = (const float*)d_in[13];
    float* out = (float*)d_out;

    const int E = in_sizes[1] / 2;
    const int M = NN;
    const int* row = ei;
    const int* col = ei + E;

    float *pX, *pCat, *pH1, *pT, *pWXr, *pWr, *pWf1r, *pW2, *pB2;
    cudaGetSymbolAddress((void**)&pX,    g_x);
    cudaGetSymbolAddress((void**)&pCat,  g_cat);
    cudaGetSymbolAddress((void**)&pH1,   g_h1);
    cudaGetSymbolAddress((void**)&pT,    g_t);
    cudaGetSymbolAddress((void**)&pWXr,  g_WXr);
    cudaGetSymbolAddress((void**)&pWr,   g_Wr);
    cudaGetSymbolAddress((void**)&pWf1r, g_Wf1r);
    cudaGetSymbolAddress((void**)&pW2,   g_Wf2p);
    cudaGetSymbolAddress((void**)&pB2,   g_bf2p);

    // ---- edge pipeline + operand prep ---------------------------------------
    k_init<<<(NN + 255) / 256, 256>>>();
    k_hist<<<(E + 255) / 256, 256>>>(row, E);
    k_scan<<<1, 1024>>>(E);
    k_bin<<<(E + 255) / 256, 256>>>(row, col, E);
    k_transpose<<<dim3((NN + 31) / 32, HF / 32), dim3(32, 8)>>>(WA);
    k_gather<<<(NN * 32 + 255) / 256, 256>>>(bA);          // xA -> cat[:, :128]
    k_prep_x<<<(int)(((size_t)NP * INF / 4 + 255) / 256), 256>>>(x);
    k_round_w<<<(HF * INF + 255) / 256, 256>>>(WX, W, Wf1);

    // ---- xX = x @ WX^T + bX  -> cat[:, 128:]  (tf32 mma) --------------------
    k_mm<128, 0, 1><<<GBLK, 256>>>(pX, INF, pWXr, bX, pCat + HF, 2 * HF, INF, nullptr);

    // ---- h1 = relu(cat @ W^T + bW + xA + xX) --------------------------------
    k_mm<128, 1, 1><<<GBLK, 256>>>(pCat, 2 * HF, pWr, bW, pH1, HF, 2 * HF, pCat);

    // ---- t = relu(h1 @ Wf1^T + bf1) -----------------------------------------
    k_mm<128, 2, 1><<<GBLK, 256>>>(pH1, HF, pWf1r, bf1, pT, HF, HF, nullptr);

    // ---- BN stats + fold -----------------------------------------------------
    k_bnstats<<<200, 256>>>(M);
    k_fold<<<1, 256>>>(gamma, beta, Wf2, bf2, M);

    // ---- out = bn(t) @ Wf2'^T + bf2' ----------------------------------------
    k_mm<64, 0, 0><<<GBLK, 256>>>(pT, HF, pW2, pB2, out, OF, HF, nullptr);
}

// round 7
// speedup vs baseline: 4.1445x; 1.7331x over previous
#include <cuda_runtime.h>
#include <cstdint>

#define NN   50000
#define NP   50048            // padded rows = 391 * 128
#define EE   800000
#define INF  512
#define HF   128
#define OF   64
#define GBLK 391              // ceil(50000/128)

// ---------------- scratch (static device globals; zero-initialized) ---------
__device__ float g_WAT [(size_t)NN * HF];      // WA transposed: [N, H]
__device__ float g_cat [(size_t)NP * 2 * HF];  // [NP, 256] (xA | xX); tail rows stay 0
__device__ float g_h1  [(size_t)NP * HF];
__device__ float g_t   [(size_t)NP * HF];
__device__ float g_Wf2p[OF * HF];              // BN-folded
__device__ float g_bf2p[OF];
__device__ int   g_hist[NN];
__device__ int   g_off [NN + 1];
__device__ int   g_cur [NN];
__device__ int   g_dst [EE];
__device__ int   g_rmin;
__device__ float g_sum  [HF];
__device__ float g_sumsq[HF];

// ---------------- helpers ----------------------------------------------------
__device__ __forceinline__ float rna(float f) {
    float r; asm("cvt.rna.tf32.f32 %0, %1;" : "=f"(r) : "f"(f)); return r;
}
__device__ __forceinline__ uint32_t rnau(float f) { return __float_as_uint(rna(f)); }
__device__ __forceinline__ uint32_t s2u(const void* p) {
    uint32_t a;
    asm("{ .reg .u64 t; cvta.to.shared.u64 t, %1; cvt.u32.u64 %0, t; }" : "=r"(a) : "l"(p));
    return a;
}
__device__ __forceinline__ void cp8(uint32_t d, const void* s) {
    asm volatile("cp.async.ca.shared.global [%0], [%1], 8;" :: "r"(d), "l"(s));
}
__device__ __forceinline__ void cp8z(uint32_t d, const void* s, int sz) {
    asm volatile("cp.async.ca.shared.global [%0], [%1], 8, %2;" :: "r"(d), "l"(s), "r"(sz));
}

// ---------------- init -------------------------------------------------------
__global__ void k_init() {
    int i = blockIdx.x * blockDim.x + threadIdx.x;
    if (i < NN) g_hist[i] = 0;
    if (blockIdx.x == 0) {
        if (threadIdx.x < HF) { g_sum[threadIdx.x] = 0.f; g_sumsq[threadIdx.x] = 0.f; }
        if (threadIdx.x == 0) g_rmin = 0x7fffffff;
    }
}

// ---------------- histogram + row min (4 edges / thread) ---------------------
__global__ void k_hist(const int* __restrict__ row, int E) {
    int base = (blockIdx.x * blockDim.x + threadIdx.x) * 4;
    int rmn = 0x7fffffff;
    #pragma unroll
    for (int u = 0; u < 4; ++u) {
        int e = base + u;
        if (e < E) {
            int r = row[e];
            rmn = min(rmn, r);
            atomicAdd(&g_hist[r], 1);
        }
    }
    unsigned wm = __reduce_min_sync(0xffffffffu, (unsigned)rmn);
    if ((threadIdx.x & 31) == 0) atomicMin(&g_rmin, (int)wm);
}

// ---------------- single-block exclusive scan --------------------------------
__global__ void k_scan(int E) {
    __shared__ int ssum[1024];
    int tid = threadIdx.x;
    const int chunk = (NN + 1023) / 1024;
    int beg = tid * chunk;
    int end = min(beg + chunk, NN);
    int s = 0;
    for (int i = beg; i < end; ++i) s += g_hist[i];
    ssum[tid] = s;
    __syncthreads();
    for (int ofs = 1; ofs < 1024; ofs <<= 1) {
        int v = (tid >= ofs) ? ssum[tid - ofs] : 0;
        __syncthreads();
        ssum[tid] += v;
        __syncthreads();
    }
    int run = (tid == 0) ? 0 : ssum[tid - 1];
    for (int i = beg; i < end; ++i) {
        g_off[i] = run; g_cur[i] = run; run += g_hist[i];
    }
    if (tid == 1023) g_off[NN] = run;
}

// ---------------- bin edges by row (4 edges / thread, independent chains) ----
__global__ void k_bin(const int* __restrict__ row, const int* __restrict__ col, int E) {
    int base = (blockIdx.x * blockDim.x + threadIdx.x) * 4;
    int r[4], c[4], p[4];
    bool ok[4];
    #pragma unroll
    for (int u = 0; u < 4; ++u) {
        int e = base + u;
        ok[u] = e < E;
        if (ok[u]) { r[u] = row[e]; c[u] = col[e]; }
    }
    #pragma unroll
    for (int u = 0; u < 4; ++u)
        if (ok[u]) p[u] = atomicAdd(&g_cur[r[u]], 1);
    #pragma unroll
    for (int u = 0; u < 4; ++u)
        if (ok[u]) g_dst[p[u]] = c[u];
}

// ---------------- transpose WA [H,N] -> WAT [N,H] ----------------------------
__global__ void k_transpose(const float* __restrict__ WA) {
    __shared__ float tile[32][33];
    int n0 = blockIdx.x * 32, h0 = blockIdx.y * 32;
    int tx = threadIdx.x, ty = threadIdx.y;
    #pragma unroll
    for (int j = 0; j < 32; j += 8) {
        int h = h0 + ty + j, n = n0 + tx;
        tile[ty + j][tx] = (n < NN) ? WA[(size_t)h * NN + n] : 0.f;
    }
    __syncthreads();
    #pragma unroll
    for (int j = 0; j < 32; j += 8) {
        int n = n0 + ty + j, h = h0 + tx;
        if (n < NN) g_WAT[(size_t)n * HF + h] = tile[tx][ty + j];
    }
}

// ---------------- gather xA = segsum(WAT[col]) + bA -> cat[:, :128] ----------
// one warp per node; unroll-4 over edges for MLP
__global__ void k_gather(const float* __restrict__ bA) {
    int w    = (blockIdx.x * blockDim.x + threadIdx.x) >> 5;
    int lane = threadIdx.x & 31;
    if (w >= NN) return;
    int bkt = w + g_rmin;
    int s = 0, e = 0;
    if (bkt < NN) { s = g_off[bkt]; e = g_off[bkt + 1]; }
    float4 acc = *(const float4*)(bA + lane * 4);
    int j = s;
    for (; j + 4 <= e; j += 4) {
        int c0 = g_dst[j], c1 = g_dst[j + 1], c2 = g_dst[j + 2], c3 = g_dst[j + 3];
        float4 v0 = *(const float4*)(g_WAT + (size_t)c0 * HF + lane * 4);
        float4 v1 = *(const float4*)(g_WAT + (size_t)c1 * HF + lane * 4);
        float4 v2 = *(const float4*)(g_WAT + (size_t)c2 * HF + lane * 4);
        float4 v3 = *(const float4*)(g_WAT + (size_t)c3 * HF + lane * 4);
        float4 p, q;
        p.x = v0.x + v1.x; p.y = v0.y + v1.y; p.z = v0.z + v1.z; p.w = v0.w + v1.w;
        q.x = v2.x + v3.x; q.y = v2.y + v3.y; q.z = v2.z + v3.z; q.w = v2.w + v3.w;
        acc.x += p.x + q.x; acc.y += p.y + q.y; acc.z += p.z + q.z; acc.w += p.w + q.w;
    }
    for (; j < e; ++j) {
        int c = g_dst[j];
        float4 v = *(const float4*)(g_WAT + (size_t)c * HF + lane * 4);
        acc.x += v.x; acc.y += v.y; acc.z += v.z; acc.w += v.w;
    }
    *((float4*)(g_cat + (size_t)w * (2 * HF) + lane * 4)) = acc;
}

// ---------------- tf32 mma.sync GEMM: C = A[M,K] @ B[N,K]^T + bias -----------
// Operands rounded to tf32 (rna) at fragment load. EPI 0: plain,
// 1: +skip(cat lo+hi)+relu, 2: relu. GUARD: zfill A rows >= NN.
// STATS: accumulate BN column sums/sumsq of stored values into g_sum/g_sumsq.
template<int BN, int EPI, int GUARD, int STATS>
__global__ __launch_bounds__(256)
void k_mm(const float* __restrict__ A, int lda,
          const float* __restrict__ B,
          const float* __restrict__ bias,
          float* __restrict__ C, int ldc, int K,
          const float* __restrict__ skip)
{
    constexpr int BM = 128, BK = 16, STR = 20;    // STR floats/row (conflict-free)
    constexpr int WXn = 4, WTN = BN / WXn;        // warp tile N: 32 or 16
    constexpr int NF = WTN / 8;                   // 4 or 2
    constexpr int MF = 4;                         // 64/16
    __shared__ float As[2][BM * STR];
    __shared__ float Bs[2][BN * STR];
    __shared__ float s_sum[BN], s_sq[BN];

    const int tid  = threadIdx.x;
    const int lane = tid & 31, warp = tid >> 5;
    const int wy = warp / WXn, wx = warp % WXn;
    const int g = lane >> 2, tg = lane & 3;
    const int bm = blockIdx.x * BM;

    if (STATS && tid < BN) { s_sum[tid] = 0.f; s_sq[tid] = 0.f; }

    float acc[MF][NF][4];
    #pragma unroll
    for (int i = 0; i < MF; ++i)
        #pragma unroll
        for (int j = 0; j < NF; ++j)
            #pragma unroll
            for (int c = 0; c < 4; ++c) acc[i][j][c] = 0.f;

    const uint32_t aS = s2u(As), bS = s2u(Bs);
    const int T = K / BK;

    auto load_tiles = [&](int t, int st) {
        const int k0 = t * BK;
        #pragma unroll
        for (int i = 0; i < BM * 8 / 256; ++i) {       // A: 4 chunks/thread
            int idx = tid + i * 256;
            int r = idx >> 3, ch = idx & 7;
            uint32_t d = aS + (uint32_t)(st * BM * STR + r * STR + ch * 2) * 4;
            if (GUARD) {
                bool v = (bm + r) < NN;
                cp8z(d, A + (v ? ((size_t)(bm + r) * lda + k0 + ch * 2) : 0), v ? 8 : 0);
            } else {
                cp8(d, A + (size_t)(bm + r) * lda + k0 + ch * 2);
            }
        }
        #pragma unroll
        for (int i = 0; i < BN * 8 / 256; ++i) {       // B
            int idx = tid + i * 256;
            int r = idx >> 3, ch = idx & 7;
            cp8(bS + (uint32_t)(st * BN * STR + r * STR + ch * 2) * 4,
                B + (size_t)r * K + k0 + ch * 2);
        }
        asm volatile("cp.async.commit_group;");
    };

    load_tiles(0, 0);

    for (int t = 0; t < T; ++t) {
        const int cur = t & 1;
        if (t + 1 < T) {
            load_tiles(t + 1, cur ^ 1);
            asm volatile("cp.async.wait_group 1;");
        } else {
            asm volatile("cp.async.wait_group 0;");
        }
        __syncthreads();

        const float* as = As[cur];
        const float* bs = Bs[cur];
        #pragma unroll
        for (int ks = 0; ks < 2; ++ks) {
            uint32_t af[MF][4], bf[NF][2];
            #pragma unroll
            for (int mf = 0; mf < MF; ++mf) {
                int r0 = (wy * 64 + mf * 16 + g) * STR + ks * 8 + tg;
                af[mf][0] = rnau(as[r0]);
                af[mf][1] = rnau(as[r0 + 8 * STR]);
                af[mf][2] = rnau(as[r0 + 4]);
                af[mf][3] = rnau(as[r0 + 8 * STR + 4]);
            }
            #pragma unroll
            for (int nf = 0; nf < NF; ++nf) {
                int rb = (wx * WTN + nf * 8 + g) * STR + ks * 8 + tg;
                bf[nf][0] = rnau(bs[rb]);
                bf[nf][1] = rnau(bs[rb + 4]);
            }
            #pragma unroll
            for (int mf = 0; mf < MF; ++mf)
                #pragma unroll
                for (int nf = 0; nf < NF; ++nf)
                    asm volatile(
                        "mma.sync.aligned.m16n8k8.row.col.f32.tf32.tf32.f32 "
                        "{%0,%1,%2,%3},{%4,%5,%6,%7},{%8,%9},{%0,%1,%2,%3};"
                        : "+f"(acc[mf][nf][0]), "+f"(acc[mf][nf][1]),
                          "+f"(acc[mf][nf][2]), "+f"(acc[mf][nf][3])
                        : "r"(af[mf][0]), "r"(af[mf][1]), "r"(af[mf][2]), "r"(af[mf][3]),
                          "r"(bf[nf][0]), "r"(bf[nf][1]));
        }
        __syncthreads();
    }

    // ---- epilogue (+ optional fused BN stats) -------------------------------
    #pragma unroll
    for (int nf = 0; nf < NF; ++nf) {
        int n0 = wx * WTN + nf * 8 + tg * 2;
        float b0 = bias[n0], b1 = bias[n0 + 1];
        float ps0 = 0.f, pq0 = 0.f, ps1 = 0.f, pq1 = 0.f;
        #pragma unroll
        for (int mf = 0; mf < MF; ++mf) {
            #pragma unroll
            for (int half = 0; half < 2; ++half) {
                int m = bm + wy * 64 + mf * 16 + g + half * 8;
                if (m >= NN) continue;
                float v0 = acc[mf][nf][half * 2 + 0] + b0;
                float v1 = acc[mf][nf][half * 2 + 1] + b1;
                if (EPI == 1) {
                    const float* sp = skip + (size_t)m * 256;
                    v0 += sp[n0]     + sp[128 + n0];
                    v1 += sp[n0 + 1] + sp[128 + n0 + 1];
                    v0 = fmaxf(v0, 0.f); v1 = fmaxf(v1, 0.f);
                } else if (EPI == 2) {
                    v0 = fmaxf(v0, 0.f); v1 = fmaxf(v1, 0.f);
                }
                *(float2*)(C + (size_t)m * ldc + n0) = make_float2(v0, v1);
                if (STATS) { ps0 += v0; pq0 += v0 * v0; ps1 += v1; pq1 += v1 * v1; }
            }
        }
        if (STATS) {
            // reduce over g (lane bits 2..4): lanes g*4+tg share column n0
            #pragma unroll
            for (int msk = 16; msk >= 4; msk >>= 1) {
                ps0 += __shfl_xor_sync(0xffffffffu, ps0, msk);
                pq0 += __shfl_xor_sync(0xffffffffu, pq0, msk);
                ps1 += __shfl_xor_sync(0xffffffffu, ps1, msk);
                pq1 += __shfl_xor_sync(0xffffffffu, pq1, msk);
            }
            if (g == 0) {
                atomicAdd(&s_sum[n0],     ps0); atomicAdd(&s_sq[n0],     pq0);
                atomicAdd(&s_sum[n0 + 1], ps1); atomicAdd(&s_sq[n0 + 1], pq1);
            }
        }
    }
    if (STATS) {
        __syncthreads();
        if (tid < BN) {
            atomicAdd(&g_sum[tid],   s_sum[tid]);
            atomicAdd(&g_sumsq[tid], s_sq[tid]);
        }
    }
}

// ---------------- fold BN affine into Wf2/bf2 --------------------------------
__global__ void k_fold(const float* __restrict__ gamma, const float* __restrict__ beta,
                       const float* __restrict__ Wf2,   const float* __restrict__ bf2,
                       int M) {
    __shared__ float a[HF], b[HF];
    int t = threadIdx.x;
    if (t < HF) {
        float inv  = 1.f / (float)M;
        float mean = g_sum[t] * inv;
        float var  = g_sumsq[t] * inv - mean * mean;
        float av   = gamma[t] * rsqrtf(var + 1e-5f);
        a[t] = av;
        b[t] = beta[t] - mean * av;
    }
    __syncthreads();
    for (int i = t; i < OF * HF; i += blockDim.x)
        g_Wf2p[i] = Wf2[i] * a[i & (HF - 1)];
    if (t < OF) {
        float s = bf2[t];
        for (int h = 0; h < HF; ++h) s += b[h] * Wf2[t * HF + h];
        g_bf2p[t] = s;
    }
}

// -----------------------------------------------------------------------------
extern "C" void kernel_launch(void* const* d_in, const int* in_sizes, int n_in,
                              void* d_out, int out_size) {
    const float* x     = (const float*)d_in[0];
    const int*   ei    = (const int*)  d_in[1];
    const float* WA    = (const float*)d_in[2];
    const float* bA    = (const float*)d_in[3];
    const float* WX    = (const float*)d_in[4];
    const float* bX    = (const float*)d_in[5];
    const float* W     = (const float*)d_in[6];
    const float* bW    = (const float*)d_in[7];
    const float* Wf1   = (const float*)d_in[8];
    const float* bf1   = (const float*)d_in[9];
    const float* gamma = (const float*)d_in[10];
    const float* beta  = (const float*)d_in[11];
    const float* Wf2   = (const float*)d_in[12];
    const float* bf2   = (const float*)d_in[13];
    float* out = (float*)d_out;

    const int E = in_sizes[1] / 2;
    const int M = NN;
    const int* row = ei;
    const int* col = ei + E;

    float *pCat, *pH1, *pT, *pW2, *pB2;
    cudaGetSymbolAddress((void**)&pCat, g_cat);
    cudaGetSymbolAddress((void**)&pH1,  g_h1);
    cudaGetSymbolAddress((void**)&pT,   g_t);
    cudaGetSymbolAddress((void**)&pW2,  g_Wf2p);
    cudaGetSymbolAddress((void**)&pB2,  g_bf2p);

    // ---- edge pipeline -------------------------------------------------------
    k_init<<<(NN + 255) / 256, 256>>>();
    k_hist<<<(E / 4 + 255) / 256, 256>>>(row, E);
    k_scan<<<1, 1024>>>(E);
    k_bin<<<(E / 4 + 255) / 256, 256>>>(row, col, E);
    k_transpose<<<dim3((NN + 31) / 32, HF / 32), dim3(32, 8)>>>(WA);
    k_gather<<<(NN * 32 + 255) / 256, 256>>>(bA);          // xA -> cat[:, :128]

    // ---- xX = x @ WX^T + bX  -> cat[:, 128:]  (raw x, guarded tail) ---------
    k_mm<128, 0, 1, 0><<<GBLK, 256>>>(x, INF, WX, bX, pCat + HF, 2 * HF, INF, nullptr);

    // ---- h1 = relu(cat @ W^T + bW + xA + xX) --------------------------------
    k_mm<128, 1, 0, 0><<<GBLK, 256>>>(pCat, 2 * HF, W, bW, pH1, HF, 2 * HF, pCat);

    // ---- t = relu(h1 @ Wf1^T + bf1)  + fused BN stats -----------------------
    k_mm<128, 2, 0, 1><<<GBLK, 256>>>(pH1, HF, Wf1, bf1, pT, HF, HF, nullptr);

    // ---- fold BN into Wf2/bf2 ------------------------------------------------
    k_fold<<<1, 256>>>(gamma, beta, Wf2, bf2, M);

    // ---- out = bn(t) @ Wf2'^T + bf2' ----------------------------------------
    k_mm<64, 0, 0, 0><<<GBLK, 256>>>(pT, HF, pW2, pB2, out, OF, HF, nullptr);
}